// round 11
// baseline (speedup 1.0000x reference)
#include <cuda_runtime.h>
#include <cuda_bf16.h>
#include <cstdint>

#define B_    8
#define L_    4096
#define DM_   512
#define H_    8
#define D_    64
#define BH_   64
#define KTOP_ 8
#define M_    (B_ * L_)   // 32768
#define WN_   (DM_ * DM_) // 262144

// ---------------- scratch (device globals; no allocations allowed) ----------
__device__ __nv_bfloat16 gx_h[M_ * DM_];   // x hi/lo, [M,512]
__device__ __nv_bfloat16 gx_l[M_ * DM_];
__device__ __nv_bfloat16 gw_h[4 * WN_];    // Wq,Wk,Wv,Wo hi/lo, each [512,512]
__device__ __nv_bfloat16 gw_l[4 * WN_];
__device__ __nv_bfloat16 gc_h[M_ * DM_];   // ctx hi/lo, [M,512]
__device__ __nv_bfloat16 gc_l[M_ * DM_];
__device__ float  g_q[BH_ * D_ * L_];      // [bh][d][l]  (transposed)
__device__ float  g_k[BH_ * D_ * L_];
__device__ float  g_v[BH_ * L_ * D_];      // [bh][l][d]
__device__ float2 g_P[BH_ * 8 * L_];
__device__ float  g_w[BH_ * KTOP_];
__device__ int    g_i[BH_ * KTOP_];

// ---------------- bf16 pack/split helpers ------------------------------------
__device__ __forceinline__ unsigned pack2(float x, float y) {
    unsigned d;
    asm("cvt.rn.bf16x2.f32 %0, %1, %2;" : "=r"(d) : "f"(y), "f"(x));
    return d;   // lo half = bf16(x), hi half = bf16(y)
}
__device__ __forceinline__ void split2(float x, float y, unsigned& h, unsigned& l) {
    h = pack2(x, y);
    float hx = __uint_as_float(h << 16);
    float hy = __uint_as_float(h & 0xFFFF0000u);
    l = pack2(x - hx, y - hy);
}

// ---------------- split kernels -----------------------------------------------
__global__ void __launch_bounds__(256) split_x_kernel(const float* __restrict__ src,
                                                      unsigned* __restrict__ hi,
                                                      unsigned* __restrict__ lo) {
    const int i = blockIdx.x * 256 + threadIdx.x;   // float4 index
    float4 v = ((const float4*)src)[i];
    unsigned h01, l01, h23, l23;
    split2(v.x, v.y, h01, l01);
    split2(v.z, v.w, h23, l23);
    ((uint2*)hi)[i] = make_uint2(h01, h23);
    ((uint2*)lo)[i] = make_uint2(l01, l23);
}

// grid (256, 4): blockIdx.y selects weight matrix
__global__ void __launch_bounds__(256) split_w_kernel(const float* __restrict__ Wq,
                                                      const float* __restrict__ Wk,
                                                      const float* __restrict__ Wv,
                                                      const float* __restrict__ Wo,
                                                      unsigned* __restrict__ hi,
                                                      unsigned* __restrict__ lo) {
    const int sel = blockIdx.y;
    const float* src = sel == 0 ? Wq : (sel == 1 ? Wk : (sel == 2 ? Wv : Wo));
    const int i = blockIdx.x * 256 + threadIdx.x;   // float4 index within matrix
    float4 v = ((const float4*)src)[i];
    unsigned h01, l01, h23, l23;
    split2(v.x, v.y, h01, l01);
    split2(v.z, v.w, h23, l23);
    const int o = sel * (WN_ / 4) + i;
    ((uint2*)hi)[o] = make_uint2(h01, h23);
    ((uint2*)lo)[o] = make_uint2(l01, l23);
}

// Swizzled byte offset inside one 4KB k-tile buffer (128 rows x 32B).
__device__ __forceinline__ int swad(int r, int hf) {
    const int line = r >> 2;
    const int chunk = (((r & 3) * 2 + hf) ^ (line & 1));
    return line * 128 + chunk * 16;
}

__device__ __forceinline__ void cp16s(uint32_t saddr, const void* g) {
    asm volatile("cp.async.cg.shared.global [%0], [%1], 16;" :: "r"(saddr), "l"(g));
}

#define LDSM4(R, a)                                                           \
    asm volatile("ldmatrix.sync.aligned.m8n8.x4.shared.b16 {%0,%1,%2,%3}, [%4];" \
                 : "=r"((R)[0]), "=r"((R)[1]), "=r"((R)[2]), "=r"((R)[3])     \
                 : "r"(a))

#define MMA16(C, Ar, B0r, B1r)                                                \
    asm volatile(                                                             \
        "mma.sync.aligned.m16n8k16.row.col.f32.bf16.bf16.f32 "                \
        "{%0,%1,%2,%3},{%4,%5,%6,%7},{%8,%9},{%0,%1,%2,%3};"                  \
        : "+f"((C)[0]), "+f"((C)[1]), "+f"((C)[2]), "+f"((C)[3])              \
        : "r"((Ar)[0]), "r"((Ar)[1]), "r"((Ar)[2]), "r"((Ar)[3]),             \
          "r"(B0r), "r"(B1r))

// ---------------- GEMM: C[m,n] = sum_k A[m,k]*W[n,k] + bias[n] ---------------
// Pre-split 3xBF16 inputs; cp.async double-buffered; ldmatrix; fp32 accum.
// MODE 0: row-major [M,512]. MODE 1: [B,H,L,D]. MODE 2: [B,H,D,L].
// smem: Ah @0, Al @8192, Wh @16384, Wl @24576; each [2 buf][4KB swizzled]
template <int MODE>
__global__ void __launch_bounds__(256) gemm512(const __nv_bfloat16* __restrict__ Ahp,
                                               const __nv_bfloat16* __restrict__ Alp,
                                               const __nv_bfloat16* __restrict__ Whp,
                                               const __nv_bfloat16* __restrict__ Wlp,
                                               const float* __restrict__ bias,
                                               float* __restrict__ out) {
    __shared__ __align__(128) unsigned char gsm[32768];
    const uint32_t sb = (uint32_t)__cvta_generic_to_shared(gsm);

    const int tid  = threadIdx.x;
    const int bm   = blockIdx.x * 128;
    const int bn   = blockIdx.y * 128;
    const int warp = tid >> 5, lane = tid & 31;
    const int g  = lane >> 2, tg = lane & 3;
    const int wm = (warp >> 1) * 32;
    const int wn = (warp & 1) * 64;

    float c[2][8][4];
#pragma unroll
    for (int i = 0; i < 2; i++)
#pragma unroll
        for (int j = 0; j < 8; j++)
#pragma unroll
            for (int r = 0; r < 4; r++) c[i][j][r] = 0.f;

    // cp.async assignment: r = tid>>1 (0..127), hf = tid&1
    const int cr = tid >> 1, chf = tid & 1;
    const int sw = swad(cr, chf);
    const __nv_bfloat16* srcA_h = Ahp + (size_t)(bm + cr) * 512 + chf * 8;
    const __nv_bfloat16* srcA_l = Alp + (size_t)(bm + cr) * 512 + chf * 8;
    const __nv_bfloat16* srcW_h = Whp + (size_t)(bn + cr) * 512 + chf * 8;
    const __nv_bfloat16* srcW_l = Wlp + (size_t)(bn + cr) * 512 + chf * 8;

    // ldmatrix per-lane addresses (relative to buf 0)
    const int lr = lane & 7, gI = lane >> 3;
    uint32_t aA[2], aW[4];
#pragma unroll
    for (int im = 0; im < 2; im++)
        aA[im] = sb + swad(wm + im * 16 + lr + (gI & 1) * 8, gI >> 1);
#pragma unroll
    for (int jp = 0; jp < 4; jp++)
        aW[jp] = sb + 16384 + swad(wn + jp * 16 + lr + ((gI >> 1) & 1) * 8, gI & 1);

    auto cp_tile = [&](int buf, int kt) {
        const int k0 = kt * 16;
        const uint32_t d = sb + buf * 4096 + sw;
        cp16s(d,         srcA_h + k0);
        cp16s(d + 8192,  srcA_l + k0);
        cp16s(d + 16384, srcW_h + k0);
        cp16s(d + 24576, srcW_l + k0);
        asm volatile("cp.async.commit_group;" ::: "memory");
    };

    auto compute = [&](int buf) {
        const uint32_t bo = buf * 4096;
        unsigned ah[2][4], al[2][4];
        LDSM4(ah[0], aA[0] + bo);
        LDSM4(ah[1], aA[1] + bo);
        LDSM4(al[0], aA[0] + 8192 + bo);
        LDSM4(al[1], aA[1] + 8192 + bo);
#pragma unroll
        for (int jp = 0; jp < 4; jp++) {
            unsigned wh[4], wl[4];
            LDSM4(wh, aW[jp] + bo);
            LDSM4(wl, aW[jp] + 8192 + bo);
#pragma unroll
            for (int im = 0; im < 2; im++) {
                MMA16(c[im][2 * jp],     ah[im], wh[0], wh[1]);
                MMA16(c[im][2 * jp],     ah[im], wl[0], wl[1]);
                MMA16(c[im][2 * jp],     al[im], wh[0], wh[1]);
                MMA16(c[im][2 * jp + 1], ah[im], wh[2], wh[3]);
                MMA16(c[im][2 * jp + 1], ah[im], wl[2], wl[3]);
                MMA16(c[im][2 * jp + 1], al[im], wh[2], wh[3]);
            }
        }
    };

    cp_tile(0, 0);
    for (int kt = 0; kt < 32; kt++) {
        const int buf = kt & 1;
        asm volatile("cp.async.wait_group 0;" ::: "memory");
        __syncthreads();
        if (kt < 31) cp_tile(buf ^ 1, kt + 1);
        compute(buf);
    }

    // epilogue
#pragma unroll
    for (int im = 0; im < 2; im++) {
#pragma unroll
        for (int jn = 0; jn < 8; jn++) {
            const int mrow = bm + wm + im * 16 + g;
            const int ncol = bn + wn + jn * 8 + 2 * tg;
            const float bv0 = bias[ncol], bv1 = bias[ncol + 1];
            float v00 = c[im][jn][0] + bv0;
            float v01 = c[im][jn][1] + bv1;
            float v10 = c[im][jn][2] + bv0;
            float v11 = c[im][jn][3] + bv1;
            if (MODE == 0) {
                out[(size_t)mrow * 512 + ncol]           = v00;
                out[(size_t)mrow * 512 + ncol + 1]       = v01;
                out[(size_t)(mrow + 8) * 512 + ncol]     = v10;
                out[(size_t)(mrow + 8) * 512 + ncol + 1] = v11;
            } else if (MODE == 1) {
                const int h = ncol >> 6, d = ncol & 63;
                const int b = mrow >> 12, l = mrow & 4095;
                size_t base = (((size_t)(b * 8 + h)) * 4096 + l) * 64 + d;
                out[base]     = v00;
                out[base + 1] = v01;
                out[base + 8 * 64]     = v10;
                out[base + 8 * 64 + 1] = v11;
            } else {
                const int b = mrow >> 12, l = mrow & 4095;
                size_t base = ((size_t)(b * 512 + ncol)) * 4096 + l;
                out[base]        = v00;
                out[base + 4096] = v01;
                out[base + 8]        = v10;
                out[base + 4096 + 8] = v11;
            }
        }
    }
}

// ---------------- radix-8 Stockham FFT, 3 smem stages + register last stage ---
__device__ __forceinline__ float2 cmul(float2 a, float2 b) {
    return make_float2(a.x * b.x - a.y * b.y, a.x * b.y + a.y * b.x);
}
__device__ __forceinline__ float2 cadd(float2 a, float2 b) {
    return make_float2(a.x + b.x, a.y + b.y);
}
__device__ __forceinline__ float2 csub(float2 a, float2 b) {
    return make_float2(a.x - b.x, a.y - b.y);
}

__device__ __forceinline__ void bfly8(const float2* a, float2* z) {
    float2 t0 = cadd(a[0], a[4]), t1 = csub(a[0], a[4]);
    float2 t2 = cadd(a[2], a[6]), t3 = csub(a[2], a[6]);
    float2 E0 = cadd(t0, t2), E2 = csub(t0, t2);
    float2 E1 = make_float2(t1.x + t3.y, t1.y - t3.x);
    float2 E3 = make_float2(t1.x - t3.y, t1.y + t3.x);
    float2 u0 = cadd(a[1], a[5]), u1 = csub(a[1], a[5]);
    float2 u2 = cadd(a[3], a[7]), u3 = csub(a[3], a[7]);
    float2 O0 = cadd(u0, u2), O2 = csub(u0, u2);
    float2 O1 = make_float2(u1.x + u3.y, u1.y - u3.x);
    float2 O3 = make_float2(u1.x - u3.y, u1.y + u3.x);
    const float r = 0.70710678118654752f;
    float2 P1 = make_float2(r * (O1.x + O1.y), r * (O1.y - O1.x));
    float2 P2 = make_float2(O2.y, -O2.x);
    float2 P3 = make_float2(r * (O3.y - O3.x), -r * (O3.x + O3.y));
    z[0] = cadd(E0, O0); z[4] = csub(E0, O0);
    z[1] = cadd(E1, P1); z[5] = csub(E1, P1);
    z[2] = cadd(E2, P2); z[6] = csub(E2, P2);
    z[3] = cadd(E3, P3); z[7] = csub(E3, P3);
}

__device__ void fft4096r8_3(float2* x, float2* y, const float2* tw, int tid) {
    int ls = 0;
#pragma unroll 1
    for (int stage = 0; stage < 3; stage++) {
        const int s = 1 << ls;
        const int q = tid & (s - 1);
        const int sp = tid - q;
        float2 a[8], z[8];
#pragma unroll
        for (int j = 0; j < 8; j++) a[j] = x[tid + j * 512];
        bfly8(a, z);
        const int ob = 8 * tid - 7 * q;
        y[ob] = z[0];
#pragma unroll
        for (int j = 1; j < 8; j++) y[ob + j * s] = cmul(tw[j * sp], z[j]);
        __syncthreads();
        float2* tmp = x; x = y; y = tmp;
        ls += 3;
    }
}

__device__ __forceinline__ void fft_last(const float2* xin, float2* z, int tid) {
    float2 a[8];
#pragma unroll
    for (int j = 0; j < 8; j++) a[j] = xin[tid + j * 512];
    bfly8(a, z);
}

// ---------------- Phase A: packed FFT(q+ik), 8 d's per block, reduce ---------
__global__ void __launch_bounds__(512) fwd_corr_kernel() {
    extern __shared__ float2 sm[];
    float2* b0 = sm;
    float2* b1 = sm + 4096;
    float2* tw = sm + 8192;
    const int tid = threadIdx.x;
    for (int j = tid; j < 4096; j += 512) {
        float s, c;
        sincospif(-(float)j / 2048.0f, &s, &c);
        tw[j] = make_float2(c, s);
    }
    const int bh = blockIdx.x >> 3, grp = blockIdx.x & 7;
    const float* qb = g_q + ((size_t)bh * 64 + grp * 8) * 4096;
    const float* kb = g_k + ((size_t)bh * 64 + grp * 8) * 4096;

    float2 acc[8];
#pragma unroll
    for (int j = 0; j < 8; j++) acc[j] = make_float2(0.f, 0.f);

    for (int dd = 0; dd < 8; dd++) {
        const float* qp = qb + (size_t)dd * 4096;
        const float* kp = kb + (size_t)dd * 4096;
        __syncthreads();
#pragma unroll
        for (int j = 0; j < 8; j++) {
            int t = tid + j * 512;
            b0[t] = make_float2(qp[t], kp[t]);
        }
        __syncthreads();
        fft4096r8_3(b0, b1, tw, tid);
        float2 z[8];
        fft_last(b1, z, tid);
#pragma unroll
        for (int r = 0; r < 8; r++) b0[tid + r * 512] = z[r];
        __syncthreads();
#pragma unroll
        for (int j = 0; j < 8; j++) {
            const int f = tid + j * 512;
            float2 Z  = z[j];
            float2 Zm = b0[(4096 - f) & 4095];
            float Qr = 0.5f * (Z.x + Zm.x);
            float Qi = 0.5f * (Z.y - Zm.y);
            float Kr = 0.5f * (Z.y + Zm.y);
            float Ki = 0.5f * (Zm.x - Z.x);
            acc[j].x += Qr * Kr + Qi * Ki;
            acc[j].y += Qr * Ki - Qi * Kr;
        }
    }
    float2* Pout = g_P + (size_t)blockIdx.x * 4096;
#pragma unroll
    for (int j = 0; j < 8; j++) Pout[tid + j * 512] = acc[j];
}

// ---------------- Phase B fused: sum partials, FFT, top-8 + softmax ----------
__global__ void __launch_bounds__(512) inv_topk_kernel() {
    extern __shared__ float2 sm[];
    float2* b0 = sm;
    float2* b1 = sm + 4096;
    float2* tw = sm + 8192;
    const int tid = threadIdx.x;
    for (int j = tid; j < 4096; j += 512) {
        float s, c;
        sincospif(-(float)j / 2048.0f, &s, &c);
        tw[j] = make_float2(c, s);
    }
    const int bh = blockIdx.x;
    const float2* Pp = g_P + (size_t)bh * 8 * 4096;
    float2 acc[8];
#pragma unroll
    for (int j = 0; j < 8; j++) acc[j] = make_float2(0.f, 0.f);
    for (int grp = 0; grp < 8; grp++) {
#pragma unroll
        for (int j = 0; j < 8; j++) {
            float2 v = Pp[(size_t)grp * 4096 + tid + j * 512];
            acc[j].x += v.x;
            acc[j].y += v.y;
        }
    }
#pragma unroll
    for (int j = 0; j < 8; j++) b0[tid + j * 512] = acc[j];
    __syncthreads();
    fft4096r8_3(b0, b1, tw, tid);
    float2 z[8];
    fft_last(b1, z, tid);

    float* scr   = (float*)sm;
    float* svals = scr + 4096;
    int*   sidx  = (int*)(svals + 512);
    __shared__ int   chosen[KTOP_];
    __shared__ float chval[KTOP_];
    __syncthreads();
    const float sc = 1.0f / (4096.0f * 64.0f);
#pragma unroll
    for (int r = 0; r < 8; r++) scr[tid + r * 512] = z[r].x * sc;
    __syncthreads();

    for (int it = 0; it < KTOP_; it++) {
        float best = -3.0e38f;
        int bi = -1;
#pragma unroll
        for (int jj = 0; jj < 8; jj++) {
            const int t = tid + jj * 512;
            float v = scr[t];
            bool used = false;
            for (int u = 0; u < it; u++)
                if (chosen[u] == t) used = true;
            if (!used && (v > best || (v == best && t < bi))) { best = v; bi = t; }
        }
        svals[tid] = best;
        sidx[tid] = bi;
        __syncthreads();
        for (int off = 256; off > 0; off >>= 1) {
            if (tid < off) {
                if (svals[tid + off] > svals[tid] ||
                    (svals[tid + off] == svals[tid] && sidx[tid + off] < sidx[tid])) {
                    svals[tid] = svals[tid + off];
                    sidx[tid]  = sidx[tid + off];
                }
            }
            __syncthreads();
        }
        if (tid == 0) { chosen[it] = sidx[0]; chval[it] = svals[0]; }
        __syncthreads();
    }
    if (tid == 0) {
        float mx = chval[0];
        float e[KTOP_], se = 0.f;
        for (int u = 0; u < KTOP_; u++) { e[u] = expf(chval[u] - mx); se += e[u]; }
        float inv = 1.0f / se;
        for (int u = 0; u < KTOP_; u++) {
            g_w[bh * KTOP_ + u] = e[u] * inv;
            g_i[bh * KTOP_ + u] = chosen[u];
        }
    }
}

// ---------------- Phase D: gather V, write split bf16 ctx ---------------------
__global__ void __launch_bounds__(256) gather_kernel() {
    const int bh = blockIdx.y;
    const int b = bh >> 3, h = bh & 7;
    const int li = threadIdx.x >> 4;     // 0..15
    const int d4 = threadIdx.x & 15;     // float4 lane
    const int l  = blockIdx.x * 16 + li;
    __shared__ float w[KTOP_];
    __shared__ int   ix[KTOP_];
    if (threadIdx.x < KTOP_) {
        w[threadIdx.x]  = g_w[bh * KTOP_ + threadIdx.x];
        ix[threadIdx.x] = g_i[bh * KTOP_ + threadIdx.x];
    }
    __syncthreads();
    const float4* vp = (const float4*)(g_v + (size_t)bh * L_ * D_);
    float4 acc = make_float4(0.f, 0.f, 0.f, 0.f);
#pragma unroll
    for (int u = 0; u < KTOP_; u++) {
        const int src = (l + ix[u]) & 4095;
        float4 v = vp[src * 16 + d4];
        const float wu = w[u];
        acc.x += wu * v.x;
        acc.y += wu * v.y;
        acc.z += wu * v.z;
        acc.w += wu * v.w;
    }
    unsigned h01, l01, h23, l23;
    split2(acc.x, acc.y, h01, l01);
    split2(acc.z, acc.w, h23, l23);
    const size_t e = (size_t)(b * L_ + l) * DM_ + h * 64 + d4 * 4;  // bf16 elt idx
    *(uint2*)((unsigned*)gc_h + (e >> 1)) = make_uint2(h01, h23);
    *(uint2*)((unsigned*)gc_l + (e >> 1)) = make_uint2(l01, l23);
}

// ---------------- launch ------------------------------------------------------
extern "C" void kernel_launch(void* const* d_in, const int* in_sizes, int n_in,
                              void* d_out, int out_size) {
    const float* x  = (const float*)d_in[0];
    const float* Wq = (const float*)d_in[1];
    const float* bq = (const float*)d_in[2];
    const float* Wk = (const float*)d_in[3];
    const float* bk = (const float*)d_in[4];
    const float* Wv = (const float*)d_in[5];
    const float* bv = (const float*)d_in[6];
    const float* Wo = (const float*)d_in[7];
    const float* bo = (const float*)d_in[8];
    float* out = (float*)d_out;

    float *qp, *kp, *vp;
    __nv_bfloat16 *xh, *xl, *wh, *wl, *ch, *cl;
    cudaGetSymbolAddress((void**)&qp, g_q);
    cudaGetSymbolAddress((void**)&kp, g_k);
    cudaGetSymbolAddress((void**)&vp, g_v);
    cudaGetSymbolAddress((void**)&xh, gx_h);
    cudaGetSymbolAddress((void**)&xl, gx_l);
    cudaGetSymbolAddress((void**)&wh, gw_h);
    cudaGetSymbolAddress((void**)&wl, gw_l);
    cudaGetSymbolAddress((void**)&ch, gc_h);
    cudaGetSymbolAddress((void**)&cl, gc_l);

    const int FFT_SMEM = 98304;
    cudaFuncSetAttribute(fwd_corr_kernel, cudaFuncAttributeMaxDynamicSharedMemorySize, FFT_SMEM);
    cudaFuncSetAttribute(inv_topk_kernel, cudaFuncAttributeMaxDynamicSharedMemorySize, FFT_SMEM);

    split_x_kernel<<<M_ * DM_ / 4 / 256, 256>>>(x, (unsigned*)xh, (unsigned*)xl);
    split_w_kernel<<<dim3(WN_ / 4 / 256, 4), 256>>>(Wq, Wk, Wv, Wo,
                                                    (unsigned*)wh, (unsigned*)wl);

    dim3 gg(M_ / 128, 4);
    gemm512<2><<<gg, 256>>>(xh, xl, wh,           wl,           bq, qp);
    gemm512<2><<<gg, 256>>>(xh, xl, wh + WN_,     wl + WN_,     bk, kp);
    gemm512<1><<<gg, 256>>>(xh, xl, wh + 2 * WN_, wl + 2 * WN_, bv, vp);
    fwd_corr_kernel<<<512, 512, FFT_SMEM>>>();
    inv_topk_kernel<<<64, 512, FFT_SMEM>>>();
    gather_kernel<<<dim3(256, 64), 256>>>();
    gemm512<0><<<gg, 256>>>(ch, cl, wh + 3 * WN_, wl + 3 * WN_, bo, out);
}

// round 12
// speedup vs baseline: 1.0701x; 1.0701x over previous
#include <cuda_runtime.h>
#include <cuda_bf16.h>
#include <cstdint>

#define B_    8
#define L_    4096
#define DM_   512
#define H_    8
#define D_    64
#define BH_   64
#define KTOP_ 8
#define M_    (B_ * L_)   // 32768
#define WN_   (DM_ * DM_) // 262144

// ---------------- scratch (device globals; no allocations allowed) ----------
__device__ __nv_bfloat16 gx_h[M_ * DM_];   // x hi/lo, [M,512]
__device__ __nv_bfloat16 gx_l[M_ * DM_];
__device__ __nv_bfloat16 gw_h[4 * WN_];    // Wq,Wk,Wv,Wo hi/lo, each [512,512]
__device__ __nv_bfloat16 gw_l[4 * WN_];
__device__ __nv_bfloat16 gc_h[M_ * DM_];   // ctx hi/lo, [M,512]
__device__ __nv_bfloat16 gc_l[M_ * DM_];
__device__ float  g_q[BH_ * D_ * L_];      // [bh][d][l]  (transposed)
__device__ float  g_k[BH_ * D_ * L_];
__device__ float  g_v[BH_ * L_ * D_];      // [bh][l][d]
__device__ float2 g_P[BH_ * 8 * L_];
__device__ float  g_w[BH_ * KTOP_];
__device__ int    g_i[BH_ * KTOP_];

// ---------------- bf16 pack/split helpers ------------------------------------
__device__ __forceinline__ unsigned pack2(float x, float y) {
    unsigned d;
    asm("cvt.rn.bf16x2.f32 %0, %1, %2;" : "=r"(d) : "f"(y), "f"(x));
    return d;   // lo half = bf16(x), hi half = bf16(y)
}
__device__ __forceinline__ void split2(float x, float y, unsigned& h, unsigned& l) {
    h = pack2(x, y);
    float hx = __uint_as_float(h << 16);
    float hy = __uint_as_float(h & 0xFFFF0000u);
    l = pack2(x - hx, y - hy);
}

// ---------------- split kernels -----------------------------------------------
__global__ void __launch_bounds__(256) split_x_kernel(const float* __restrict__ src,
                                                      unsigned* __restrict__ hi,
                                                      unsigned* __restrict__ lo) {
    const int i = blockIdx.x * 256 + threadIdx.x;   // float4 index
    float4 v = ((const float4*)src)[i];
    unsigned h01, l01, h23, l23;
    split2(v.x, v.y, h01, l01);
    split2(v.z, v.w, h23, l23);
    ((uint2*)hi)[i] = make_uint2(h01, h23);
    ((uint2*)lo)[i] = make_uint2(l01, l23);
}

// grid (256, 4): blockIdx.y selects weight matrix
__global__ void __launch_bounds__(256) split_w_kernel(const float* __restrict__ Wq,
                                                      const float* __restrict__ Wk,
                                                      const float* __restrict__ Wv,
                                                      const float* __restrict__ Wo,
                                                      unsigned* __restrict__ hi,
                                                      unsigned* __restrict__ lo) {
    const int sel = blockIdx.y;
    const float* src = sel == 0 ? Wq : (sel == 1 ? Wk : (sel == 2 ? Wv : Wo));
    const int i = blockIdx.x * 256 + threadIdx.x;
    float4 v = ((const float4*)src)[i];
    unsigned h01, l01, h23, l23;
    split2(v.x, v.y, h01, l01);
    split2(v.z, v.w, h23, l23);
    const int o = sel * (WN_ / 4) + i;
    ((uint2*)hi)[o] = make_uint2(h01, h23);
    ((uint2*)lo)[o] = make_uint2(l01, l23);
}

// Swizzled byte offset inside one 4KB k-tile buffer (128 rows x 32B).
__device__ __forceinline__ int swad(int r, int hf) {
    const int line = r >> 2;
    const int chunk = (((r & 3) * 2 + hf) ^ (line & 1));
    return line * 128 + chunk * 16;
}

__device__ __forceinline__ void cp16s(uint32_t saddr, const void* g) {
    asm volatile("cp.async.cg.shared.global [%0], [%1], 16;" :: "r"(saddr), "l"(g));
}

#define LDSM4(R, a)                                                           \
    asm volatile("ldmatrix.sync.aligned.m8n8.x4.shared.b16 {%0,%1,%2,%3}, [%4];" \
                 : "=r"((R)[0]), "=r"((R)[1]), "=r"((R)[2]), "=r"((R)[3])     \
                 : "r"(a))

#define MMA16(C, Ar, B0r, B1r)                                                \
    asm volatile(                                                             \
        "mma.sync.aligned.m16n8k16.row.col.f32.bf16.bf16.f32 "                \
        "{%0,%1,%2,%3},{%4,%5,%6,%7},{%8,%9},{%0,%1,%2,%3};"                  \
        : "+f"((C)[0]), "+f"((C)[1]), "+f"((C)[2]), "+f"((C)[3])              \
        : "r"((Ar)[0]), "r"((Ar)[1]), "r"((Ar)[2]), "r"((Ar)[3]),             \
          "r"(B0r), "r"(B1r))

// ---------------- GEMM: C[m,n] = sum_k A[m,k]*W[n,k] + bias[n] ---------------
// Pre-split 3xBF16; 3-stage cp.async pipeline; ldmatrix; interleaved MMAs.
// MODE 0: row-major [M,512]. MODE 1: [B,H,L,D]. MODE 2: [B,H,D,L].
// smem: Ah @0, Al @12288, Wh @24576, Wl @36864; each [3 stage][4KB swizzled]
template <int MODE>
__global__ void __launch_bounds__(256, 2) gemm512(const __nv_bfloat16* __restrict__ Ahp,
                                                  const __nv_bfloat16* __restrict__ Alp,
                                                  const __nv_bfloat16* __restrict__ Whp,
                                                  const __nv_bfloat16* __restrict__ Wlp,
                                                  const float* __restrict__ bias,
                                                  float* __restrict__ out) {
    __shared__ __align__(128) unsigned char gsm[49152];
    const uint32_t sb = (uint32_t)__cvta_generic_to_shared(gsm);

    const int tid  = threadIdx.x;
    const int bm   = blockIdx.x * 128;
    const int bn   = blockIdx.y * 128;
    const int warp = tid >> 5, lane = tid & 31;
    const int g  = lane >> 2, tg = lane & 3;
    const int wm = (warp >> 1) * 32;
    const int wn = (warp & 1) * 64;

    float c[2][8][4];
#pragma unroll
    for (int i = 0; i < 2; i++)
#pragma unroll
        for (int j = 0; j < 8; j++)
#pragma unroll
            for (int r = 0; r < 4; r++) c[i][j][r] = 0.f;

    // cp.async assignment: r = tid>>1 (0..127), hf = tid&1
    const int cr = tid >> 1, chf = tid & 1;
    const int sw = swad(cr, chf);
    const __nv_bfloat16* srcA_h = Ahp + (size_t)(bm + cr) * 512 + chf * 8;
    const __nv_bfloat16* srcA_l = Alp + (size_t)(bm + cr) * 512 + chf * 8;
    const __nv_bfloat16* srcW_h = Whp + (size_t)(bn + cr) * 512 + chf * 8;
    const __nv_bfloat16* srcW_l = Wlp + (size_t)(bn + cr) * 512 + chf * 8;

    // ldmatrix per-lane addresses (relative to stage 0)
    const int lr = lane & 7, gI = lane >> 3;
    uint32_t aA[2], aW[4];
#pragma unroll
    for (int im = 0; im < 2; im++)
        aA[im] = sb + swad(wm + im * 16 + lr + (gI & 1) * 8, gI >> 1);
#pragma unroll
    for (int jp = 0; jp < 4; jp++)
        aW[jp] = sb + 24576 + swad(wn + jp * 16 + lr + ((gI >> 1) & 1) * 8, gI & 1);

    auto cp_tile = [&](int buf, int kt) {
        const int k0 = kt * 16;
        const uint32_t d = sb + buf * 4096 + sw;
        cp16s(d,         srcA_h + k0);
        cp16s(d + 12288, srcA_l + k0);
        cp16s(d + 24576, srcW_h + k0);
        cp16s(d + 36864, srcW_l + k0);
        asm volatile("cp.async.commit_group;" ::: "memory");
    };

    auto compute = [&](int buf) {
        const uint32_t bo = buf * 4096;
        unsigned ah[2][4], al[2][4];
        LDSM4(ah[0], aA[0] + bo);
        LDSM4(ah[1], aA[1] + bo);
        LDSM4(al[0], aA[0] + 12288 + bo);
        LDSM4(al[1], aA[1] + 12288 + bo);
#pragma unroll
        for (int jp = 0; jp < 4; jp++) {
            unsigned wh[4], wl[4];
            LDSM4(wh, aW[jp] + bo);
            LDSM4(wl, aW[jp] + 12288 + bo);
            // interleaved: 4 independent accumulators between dependent reuses;
            // per-accumulator order (hh, hl, lh) unchanged -> bit-identical
            MMA16(c[0][2 * jp],     ah[0], wh[0], wh[1]);
            MMA16(c[1][2 * jp],     ah[1], wh[0], wh[1]);
            MMA16(c[0][2 * jp + 1], ah[0], wh[2], wh[3]);
            MMA16(c[1][2 * jp + 1], ah[1], wh[2], wh[3]);
            MMA16(c[0][2 * jp],     ah[0], wl[0], wl[1]);
            MMA16(c[1][2 * jp],     ah[1], wl[0], wl[1]);
            MMA16(c[0][2 * jp + 1], ah[0], wl[2], wl[3]);
            MMA16(c[1][2 * jp + 1], ah[1], wl[2], wl[3]);
            MMA16(c[0][2 * jp],     al[0], wh[0], wh[1]);
            MMA16(c[1][2 * jp],     al[1], wh[0], wh[1]);
            MMA16(c[0][2 * jp + 1], al[0], wh[2], wh[3]);
            MMA16(c[1][2 * jp + 1], al[1], wh[2], wh[3]);
        }
    };

    cp_tile(0, 0);
    cp_tile(1, 1);
#pragma unroll 1
    for (int kt = 0; kt < 32; kt++) {
        const int buf = kt % 3;
        if (kt < 30) {
            asm volatile("cp.async.wait_group 1;" ::: "memory");
        } else {
            asm volatile("cp.async.wait_group 0;" ::: "memory");
        }
        __syncthreads();
        if (kt < 30) cp_tile((kt + 2) % 3, kt + 2);
        compute(buf);
    }

    // epilogue
#pragma unroll
    for (int im = 0; im < 2; im++) {
#pragma unroll
        for (int jn = 0; jn < 8; jn++) {
            const int mrow = bm + wm + im * 16 + g;
            const int ncol = bn + wn + jn * 8 + 2 * tg;
            const float bv0 = bias[ncol], bv1 = bias[ncol + 1];
            float v00 = c[im][jn][0] + bv0;
            float v01 = c[im][jn][1] + bv1;
            float v10 = c[im][jn][2] + bv0;
            float v11 = c[im][jn][3] + bv1;
            if (MODE == 0) {
                out[(size_t)mrow * 512 + ncol]           = v00;
                out[(size_t)mrow * 512 + ncol + 1]       = v01;
                out[(size_t)(mrow + 8) * 512 + ncol]     = v10;
                out[(size_t)(mrow + 8) * 512 + ncol + 1] = v11;
            } else if (MODE == 1) {
                const int h = ncol >> 6, d = ncol & 63;
                const int b = mrow >> 12, l = mrow & 4095;
                size_t base = (((size_t)(b * 8 + h)) * 4096 + l) * 64 + d;
                out[base]     = v00;
                out[base + 1] = v01;
                out[base + 8 * 64]     = v10;
                out[base + 8 * 64 + 1] = v11;
            } else {
                const int b = mrow >> 12, l = mrow & 4095;
                size_t base = ((size_t)(b * 512 + ncol)) * 4096 + l;
                out[base]        = v00;
                out[base + 4096] = v01;
                out[base + 8]        = v10;
                out[base + 4096 + 8] = v11;
            }
        }
    }
}

// ---------------- radix-8 Stockham FFT, 3 smem stages + register last stage ---
__device__ __forceinline__ float2 cmul(float2 a, float2 b) {
    return make_float2(a.x * b.x - a.y * b.y, a.x * b.y + a.y * b.x);
}
__device__ __forceinline__ float2 cadd(float2 a, float2 b) {
    return make_float2(a.x + b.x, a.y + b.y);
}
__device__ __forceinline__ float2 csub(float2 a, float2 b) {
    return make_float2(a.x - b.x, a.y - b.y);
}

__device__ __forceinline__ void bfly8(const float2* a, float2* z) {
    float2 t0 = cadd(a[0], a[4]), t1 = csub(a[0], a[4]);
    float2 t2 = cadd(a[2], a[6]), t3 = csub(a[2], a[6]);
    float2 E0 = cadd(t0, t2), E2 = csub(t0, t2);
    float2 E1 = make_float2(t1.x + t3.y, t1.y - t3.x);
    float2 E3 = make_float2(t1.x - t3.y, t1.y + t3.x);
    float2 u0 = cadd(a[1], a[5]), u1 = csub(a[1], a[5]);
    float2 u2 = cadd(a[3], a[7]), u3 = csub(a[3], a[7]);
    float2 O0 = cadd(u0, u2), O2 = csub(u0, u2);
    float2 O1 = make_float2(u1.x + u3.y, u1.y - u3.x);
    float2 O3 = make_float2(u1.x - u3.y, u1.y + u3.x);
    const float r = 0.70710678118654752f;
    float2 P1 = make_float2(r * (O1.x + O1.y), r * (O1.y - O1.x));
    float2 P2 = make_float2(O2.y, -O2.x);
    float2 P3 = make_float2(r * (O3.y - O3.x), -r * (O3.x + O3.y));
    z[0] = cadd(E0, O0); z[4] = csub(E0, O0);
    z[1] = cadd(E1, P1); z[5] = csub(E1, P1);
    z[2] = cadd(E2, P2); z[6] = csub(E2, P2);
    z[3] = cadd(E3, P3); z[7] = csub(E3, P3);
}

__device__ void fft4096r8_3(float2* x, float2* y, const float2* tw, int tid) {
    int ls = 0;
#pragma unroll 1
    for (int stage = 0; stage < 3; stage++) {
        const int s = 1 << ls;
        const int q = tid & (s - 1);
        const int sp = tid - q;
        float2 a[8], z[8];
#pragma unroll
        for (int j = 0; j < 8; j++) a[j] = x[tid + j * 512];
        bfly8(a, z);
        const int ob = 8 * tid - 7 * q;
        y[ob] = z[0];
#pragma unroll
        for (int j = 1; j < 8; j++) y[ob + j * s] = cmul(tw[j * sp], z[j]);
        __syncthreads();
        float2* tmp = x; x = y; y = tmp;
        ls += 3;
    }
}

__device__ __forceinline__ void fft_last(const float2* xin, float2* z, int tid) {
    float2 a[8];
#pragma unroll
    for (int j = 0; j < 8; j++) a[j] = xin[tid + j * 512];
    bfly8(a, z);
}

// ---------------- Phase A: packed FFT(q+ik), 8 d's per block, reduce ---------
__global__ void __launch_bounds__(512) fwd_corr_kernel() {
    extern __shared__ float2 sm[];
    float2* b0 = sm;
    float2* b1 = sm + 4096;
    float2* tw = sm + 8192;
    const int tid = threadIdx.x;
    for (int j = tid; j < 4096; j += 512) {
        float s, c;
        sincospif(-(float)j / 2048.0f, &s, &c);
        tw[j] = make_float2(c, s);
    }
    const int bh = blockIdx.x >> 3, grp = blockIdx.x & 7;
    const float* qb = g_q + ((size_t)bh * 64 + grp * 8) * 4096;
    const float* kb = g_k + ((size_t)bh * 64 + grp * 8) * 4096;

    float2 acc[8];
#pragma unroll
    for (int j = 0; j < 8; j++) acc[j] = make_float2(0.f, 0.f);

    for (int dd = 0; dd < 8; dd++) {
        const float* qp = qb + (size_t)dd * 4096;
        const float* kp = kb + (size_t)dd * 4096;
        __syncthreads();
#pragma unroll
        for (int j = 0; j < 8; j++) {
            int t = tid + j * 512;
            b0[t] = make_float2(qp[t], kp[t]);
        }
        __syncthreads();
        fft4096r8_3(b0, b1, tw, tid);
        float2 z[8];
        fft_last(b1, z, tid);
#pragma unroll
        for (int r = 0; r < 8; r++) b0[tid + r * 512] = z[r];
        __syncthreads();
#pragma unroll
        for (int j = 0; j < 8; j++) {
            const int f = tid + j * 512;
            float2 Z  = z[j];
            float2 Zm = b0[(4096 - f) & 4095];
            float Qr = 0.5f * (Z.x + Zm.x);
            float Qi = 0.5f * (Z.y - Zm.y);
            float Kr = 0.5f * (Z.y + Zm.y);
            float Ki = 0.5f * (Zm.x - Z.x);
            acc[j].x += Qr * Kr + Qi * Ki;
            acc[j].y += Qr * Ki - Qi * Kr;
        }
    }
    float2* Pout = g_P + (size_t)blockIdx.x * 4096;
#pragma unroll
    for (int j = 0; j < 8; j++) Pout[tid + j * 512] = acc[j];
}

// ---------------- Phase B fused: sum partials, FFT, top-8 + softmax ----------
__global__ void __launch_bounds__(512) inv_topk_kernel() {
    extern __shared__ float2 sm[];
    float2* b0 = sm;
    float2* b1 = sm + 4096;
    float2* tw = sm + 8192;
    const int tid = threadIdx.x;
    for (int j = tid; j < 4096; j += 512) {
        float s, c;
        sincospif(-(float)j / 2048.0f, &s, &c);
        tw[j] = make_float2(c, s);
    }
    const int bh = blockIdx.x;
    const float2* Pp = g_P + (size_t)bh * 8 * 4096;
    float2 acc[8];
#pragma unroll
    for (int j = 0; j < 8; j++) acc[j] = make_float2(0.f, 0.f);
    for (int grp = 0; grp < 8; grp++) {
#pragma unroll
        for (int j = 0; j < 8; j++) {
            float2 v = Pp[(size_t)grp * 4096 + tid + j * 512];
            acc[j].x += v.x;
            acc[j].y += v.y;
        }
    }
#pragma unroll
    for (int j = 0; j < 8; j++) b0[tid + j * 512] = acc[j];
    __syncthreads();
    fft4096r8_3(b0, b1, tw, tid);
    float2 z[8];
    fft_last(b1, z, tid);

    float* scr   = (float*)sm;
    float* svals = scr + 4096;
    int*   sidx  = (int*)(svals + 512);
    __shared__ int   chosen[KTOP_];
    __shared__ float chval[KTOP_];
    __syncthreads();
    const float sc = 1.0f / (4096.0f * 64.0f);
#pragma unroll
    for (int r = 0; r < 8; r++) scr[tid + r * 512] = z[r].x * sc;
    __syncthreads();

    for (int it = 0; it < KTOP_; it++) {
        float best = -3.0e38f;
        int bi = -1;
#pragma unroll
        for (int jj = 0; jj < 8; jj++) {
            const int t = tid + jj * 512;
            float v = scr[t];
            bool used = false;
            for (int u = 0; u < it; u++)
                if (chosen[u] == t) used = true;
            if (!used && (v > best || (v == best && t < bi))) { best = v; bi = t; }
        }
        svals[tid] = best;
        sidx[tid] = bi;
        __syncthreads();
        for (int off = 256; off > 0; off >>= 1) {
            if (tid < off) {
                if (svals[tid + off] > svals[tid] ||
                    (svals[tid + off] == svals[tid] && sidx[tid + off] < sidx[tid])) {
                    svals[tid] = svals[tid + off];
                    sidx[tid]  = sidx[tid + off];
                }
            }
            __syncthreads();
        }
        if (tid == 0) { chosen[it] = sidx[0]; chval[it] = svals[0]; }
        __syncthreads();
    }
    if (tid == 0) {
        float mx = chval[0];
        float e[KTOP_], se = 0.f;
        for (int u = 0; u < KTOP_; u++) { e[u] = expf(chval[u] - mx); se += e[u]; }
        float inv = 1.0f / se;
        for (int u = 0; u < KTOP_; u++) {
            g_w[bh * KTOP_ + u] = e[u] * inv;
            g_i[bh * KTOP_ + u] = chosen[u];
        }
    }
}

// ---------------- Phase D: gather V, write split bf16 ctx ---------------------
__global__ void __launch_bounds__(256) gather_kernel() {
    const int bh = blockIdx.y;
    const int b = bh >> 3, h = bh & 7;
    const int li = threadIdx.x >> 4;
    const int d4 = threadIdx.x & 15;
    const int l  = blockIdx.x * 16 + li;
    __shared__ float w[KTOP_];
    __shared__ int   ix[KTOP_];
    if (threadIdx.x < KTOP_) {
        w[threadIdx.x]  = g_w[bh * KTOP_ + threadIdx.x];
        ix[threadIdx.x] = g_i[bh * KTOP_ + threadIdx.x];
    }
    __syncthreads();
    const float4* vp = (const float4*)(g_v + (size_t)bh * L_ * D_);
    float4 acc = make_float4(0.f, 0.f, 0.f, 0.f);
#pragma unroll
    for (int u = 0; u < KTOP_; u++) {
        const int src = (l + ix[u]) & 4095;
        float4 v = vp[src * 16 + d4];
        const float wu = w[u];
        acc.x += wu * v.x;
        acc.y += wu * v.y;
        acc.z += wu * v.z;
        acc.w += wu * v.w;
    }
    unsigned h01, l01, h23, l23;
    split2(acc.x, acc.y, h01, l01);
    split2(acc.z, acc.w, h23, l23);
    const size_t e = (size_t)(b * L_ + l) * DM_ + h * 64 + d4 * 4;
    *(uint2*)((unsigned*)gc_h + (e >> 1)) = make_uint2(h01, h23);
    *(uint2*)((unsigned*)gc_l + (e >> 1)) = make_uint2(l01, l23);
}

// ---------------- launch ------------------------------------------------------
extern "C" void kernel_launch(void* const* d_in, const int* in_sizes, int n_in,
                              void* d_out, int out_size) {
    const float* x  = (const float*)d_in[0];
    const float* Wq = (const float*)d_in[1];
    const float* bq = (const float*)d_in[2];
    const float* Wk = (const float*)d_in[3];
    const float* bk = (const float*)d_in[4];
    const float* Wv = (const float*)d_in[5];
    const float* bv = (const float*)d_in[6];
    const float* Wo = (const float*)d_in[7];
    const float* bo = (const float*)d_in[8];
    float* out = (float*)d_out;

    float *qp, *kp, *vp;
    __nv_bfloat16 *xh, *xl, *wh, *wl, *ch, *cl;
    cudaGetSymbolAddress((void**)&qp, g_q);
    cudaGetSymbolAddress((void**)&kp, g_k);
    cudaGetSymbolAddress((void**)&vp, g_v);
    cudaGetSymbolAddress((void**)&xh, gx_h);
    cudaGetSymbolAddress((void**)&xl, gx_l);
    cudaGetSymbolAddress((void**)&wh, gw_h);
    cudaGetSymbolAddress((void**)&wl, gw_l);
    cudaGetSymbolAddress((void**)&ch, gc_h);
    cudaGetSymbolAddress((void**)&cl, gc_l);

    const int FFT_SMEM = 98304;
    cudaFuncSetAttribute(fwd_corr_kernel, cudaFuncAttributeMaxDynamicSharedMemorySize, FFT_SMEM);
    cudaFuncSetAttribute(inv_topk_kernel, cudaFuncAttributeMaxDynamicSharedMemorySize, FFT_SMEM);

    split_x_kernel<<<M_ * DM_ / 4 / 256, 256>>>(x, (unsigned*)xh, (unsigned*)xl);
    split_w_kernel<<<dim3(WN_ / 4 / 256, 4), 256>>>(Wq, Wk, Wv, Wo,
                                                    (unsigned*)wh, (unsigned*)wl);

    dim3 gg(M_ / 128, 4);
    gemm512<2><<<gg, 256>>>(xh, xl, wh,           wl,           bq, qp);
    gemm512<2><<<gg, 256>>>(xh, xl, wh + WN_,     wl + WN_,     bk, kp);
    gemm512<1><<<gg, 256>>>(xh, xl, wh + 2 * WN_, wl + 2 * WN_, bv, vp);
    fwd_corr_kernel<<<512, 512, FFT_SMEM>>>();
    inv_topk_kernel<<<64, 512, FFT_SMEM>>>();
    gather_kernel<<<dim3(256, 64), 256>>>();
    gemm512<0><<<gg, 256>>>(ch, cl, wh + 3 * WN_, wl + 3 * WN_, bo, out);
}